// round 9
// baseline (speedup 1.0000x reference)
#include <cuda_runtime.h>
#include <cuda_fp16.h>
#include <math.h>

#define HIDDEN 64
#define MBATCH 32
#define ATOM   64
#define NUM_RBF 300

#define S_INT   512
#define TAB_ROWS 513                    // row s = h(s*H_STEP), s in [0,512]
#define H_STEP  (10.0f / 512.0f)
#define INV_H   51.2f

typedef unsigned long long u64;

// device scratch (no allocations allowed)
__device__ __align__(16) unsigned g_table_h[515 * 32];   // fp16x2 table, row=128B
__device__ __align__(16) float g_v1[MBATCH * ATOM * HIDDEN];
__device__ __align__(16) float g_W2t[HIDDEN * HIDDEN];
__device__ __align__(16) float g_W3t[HIDDEN * HIDDEN];

__device__ __forceinline__ float softplus_f(float v) {
    return fmaxf(v, 0.0f) + log1pf(expf(-fabsf(v)));
}

// packed f32x2 helpers (Blackwell FFMA2 / FADD2)
__device__ __forceinline__ u64 fma2(u64 a, u64 b, u64 c) {
    u64 d; asm("fma.rn.f32x2 %0, %1, %2, %3;" : "=l"(d) : "l"(a), "l"(b), "l"(c)); return d;
}
__device__ __forceinline__ u64 add2(u64 a, u64 b) {
    u64 d; asm("add.rn.f32x2 %0, %1, %2;" : "=l"(d) : "l"(a), "l"(b)); return d;
}
__device__ __forceinline__ u64 pack2(float a, float b) {
    u64 d; asm("mov.b64 %0, {%1, %2};" : "=l"(d) : "f"(a), "f"(b)); return d;
}
__device__ __forceinline__ float2 unpk2(u64 v) {
    float2 f; asm("mov.b64 {%0, %1}, %2;" : "=f"(f.x), "=f"(f.y) : "l"(v)); return f;
}
__device__ __forceinline__ u64 dup2(float v) {
    u64 d; asm("mov.b64 %0, {%1, %1};" : "=l"(d) : "f"(v)); return d;
}
__device__ __forceinline__ unsigned h2bits(float w) {
    __half2 h = __float2half2_rn(w);
    return *reinterpret_cast<unsigned*>(&h);
}
__device__ __forceinline__ __half2 bits2h(unsigned u) {
    return *reinterpret_cast<__half2*>(&u);
}

// ---------------------------------------------------------------------------
// Prep kernel, 512 threads/block:
//   blocks [0,65):    h(d) table (fp16), 8 samples/block
//   blocks [65,129):  v1 = x@W1^T + b1
//   block 129:        transpose W2, W3
// All global staging vectorized (float4) + unrolled for MLP.
// ---------------------------------------------------------------------------
#define TAB_BLOCKS 65
#define V1_BLOCKS  64
#define PREP_BLOCKS (TAB_BLOCKS + V1_BLOCKS + 1)
#define PREP_SMEM ((64*301 + 64*65 + 8*304 + 8*64) * 4)

__global__ void __launch_bounds__(512) prep_kernel(
    const float* __restrict__ x,  const float* __restrict__ W1, const float* __restrict__ b1,
    const float* __restrict__ W2, const float* __restrict__ W3,
    const float* __restrict__ Wd1, const float* __restrict__ bd1,
    const float* __restrict__ Wd2, const float* __restrict__ bd2)
{
    extern __shared__ float sh[];
    const int tid = threadIdx.x;
    const int b = blockIdx.x;

    if (b < TAB_BLOCKS) {
        float* Wd1_s = sh;                   // 64 x 301 (padded)
        float* Wd2_s = Wd1_s + 64 * 301;     // 64 x 65
        float* rbf_s = Wd2_s + 64 * 65;      // 8 x 304
        float* g_s   = rbf_s + 8 * 304;      // 8 x 64

        // Wd1: 64x300 = 4800 float4 loads, unrolled for MLP
        {
            const float4* w4 = (const float4*)Wd1;
            #pragma unroll 4
            for (int idx = tid; idx < 4800; idx += 512) {
                float4 v = w4[idx];
                int e = idx << 2;
                int cc = e / NUM_RBF;
                int r  = e - cc * NUM_RBF;
                float* dstp = Wd1_s + cc * 301 + r;
                dstp[0] = v.x; dstp[1] = v.y; dstp[2] = v.z; dstp[3] = v.w;
            }
        }
        // Wd2: 64x64 = 1024 float4
        {
            const float4* w4 = (const float4*)Wd2;
            #pragma unroll 2
            for (int idx = tid; idx < 1024; idx += 512) {
                float4 v = w4[idx];
                int e = idx << 2;
                float* dstp = Wd2_s + (e >> 6) * 65 + (e & 63);
                dstp[0] = v.x; dstp[1] = v.y; dstp[2] = v.z; dstp[3] = v.w;
            }
        }
        const int s0 = b * 8;
        #pragma unroll 2
        for (int idx = tid; idx < 8 * NUM_RBF; idx += 512) {
            int qq = idx / NUM_RBF;
            int r  = idx - qq * NUM_RBF;
            float dd = (float)(s0 + qq) * H_STEP;
            float u = dd - 0.1f * (float)r;
            rbf_s[qq * 304 + r] = __expf(-10.0f * u * u);
        }
        __syncthreads();

        const int q = tid >> 6;
        const int c = tid & 63;
        const int s = s0 + q;
        const float d = (float)s * H_STEP;
        // only RBFs within |d - 0.1r| <= 1.5 contribute (> 1.7e-10)
        int rlo = (int)ceilf((d - 1.5f) * 10.0f); if (rlo < 0) rlo = 0;
        int rhi = (int)floorf((d + 1.5f) * 10.0f); if (rhi > NUM_RBF - 1) rhi = NUM_RBF - 1;
        float p = bd1[c];
        const float* wrow = Wd1_s + c * 301;
        const float* rrow = rbf_s + q * 304;
        #pragma unroll 4
        for (int r = rlo; r <= rhi; r++) p = fmaf(wrow[r], rrow[r], p);
        g_s[q * 64 + c] = softplus_f(p);
        __syncthreads();

        float qv = bd2[c];
        const float* w2row = Wd2_s + c * 65;
        const float* gg = g_s + q * 64;
        #pragma unroll 8
        for (int k = 0; k < 64; k++) qv = fmaf(w2row[k], gg[k], qv);
        if (s < TAB_ROWS)
            ((__half*)g_table_h)[s * 64 + c] = __float2half_rn(softplus_f(qv));
    } else if (b < TAB_BLOCKS + V1_BLOCKS) {
        const int v = b - TAB_BLOCKS;
        const int m = v >> 1, half = v & 1;
        float* W1p = sh;                 // 64 x 68 padded
        float* xp  = sh + 64 * 68;       // 32 x 68

        {
            const float4* w4 = (const float4*)W1;
            #pragma unroll 2
            for (int idx = tid; idx < 1024; idx += 512) {
                float4 vv = w4[idx];
                int e = idx << 2;
                float* dstp = W1p + (e >> 6) * 68 + (e & 63);
                dstp[0] = vv.x; dstp[1] = vv.y; dstp[2] = vv.z; dstp[3] = vv.w;
            }
            const float4* x4 = (const float4*)(x + m * 4096 + half * 2048);
            {
                int idx = tid;
                float4 vv = x4[idx];
                int e = idx << 2;
                float* dstp = xp + (e >> 6) * 68 + (e & 63);
                dstp[0] = vv.x; dstp[1] = vv.y; dstp[2] = vv.z; dstp[3] = vv.w;
            }
        }
        __syncthreads();

        const int ii = tid & 31;
        const int oh = tid >> 5;
        float4 acc = make_float4(0.f, 0.f, 0.f, 0.f);
        const float* xr = xp + ii * 68;
        const float* wr = W1p + oh * 4 * 68;
        #pragma unroll
        for (int c4 = 0; c4 < 16; c4++) {
            float4 xv = *(const float4*)(xr + c4 * 4);
            float4 w0 = *(const float4*)(wr + 0 * 68 + c4 * 4);
            float4 w1 = *(const float4*)(wr + 1 * 68 + c4 * 4);
            float4 w2 = *(const float4*)(wr + 2 * 68 + c4 * 4);
            float4 w3 = *(const float4*)(wr + 3 * 68 + c4 * 4);
            acc.x = fmaf(xv.x, w0.x, fmaf(xv.y, w0.y, fmaf(xv.z, w0.z, fmaf(xv.w, w0.w, acc.x))));
            acc.y = fmaf(xv.x, w1.x, fmaf(xv.y, w1.y, fmaf(xv.z, w1.z, fmaf(xv.w, w1.w, acc.y))));
            acc.z = fmaf(xv.x, w2.x, fmaf(xv.y, w2.y, fmaf(xv.z, w2.z, fmaf(xv.w, w2.w, acc.z))));
            acc.w = fmaf(xv.x, w3.x, fmaf(xv.y, w3.y, fmaf(xv.z, w3.z, fmaf(xv.w, w3.w, acc.w))));
        }
        float4 bv = *(const float4*)(b1 + oh * 4);
        acc.x += bv.x; acc.y += bv.y; acc.z += bv.z; acc.w += bv.w;
        *(float4*)(g_v1 + (m * 64 + half * 32 + ii) * 64 + oh * 4) = acc;
    } else {
        // transpose W2, W3: coalesced reads, scattered writes
        #pragma unroll 8
        for (int idx = tid; idx < 8192; idx += 512) {
            const float* src = (idx < 4096) ? W2 : W3;
            float* dst = (idx < 4096) ? g_W2t : g_W3t;
            int e = idx & 4095;
            dst[(e & 63) * 64 + (e >> 6)] = src[e];   // dst[c][o] = src[o][c]
        }
    }
}

// ---------------------------------------------------------------------------
// Main kernel (R5, best known): 128 blocks = (m, j-group of 16),
// 1024 threads (32 warps). Warp = (ihalf, jj); lane = channel pair.
// Quadratic 3-tap fp16 interpolation, conflict-free smem layout.
// ---------------------------------------------------------------------------
// smem floats: TAB 16480 | V1 4096 | W4 4096 | PART 2048 | PAIR 1024 |
// V2 1024 | B2 64 | B3 64  = 28896 floats = 115584 B
#define MAIN_SMEM (28896 * 4)

__global__ void __launch_bounds__(1024) main_kernel(
    const float* __restrict__ x, const float* __restrict__ dist,
    const float* __restrict__ b2, const float* __restrict__ b3,
    float* __restrict__ out)
{
    extern __shared__ float sh[];
    unsigned* TABu = (unsigned*)sh;       // fp16 table; reused as W2T/W3T later
    float* V1s  = sh + 16480;             // 4096
    float* W4s  = V1s + 4096;             // 4096 : per-pair (wm,w0,wp h2-bits, koff)
    float* PARTs= W4s + 4096;             // 2048 : 2-way u64 partials
    float* PAIRs= PARTs + 2048;           // 1024
    float* V2s  = PAIRs + 1024;           // 1024
    float* B2s  = V2s + 1024;             // 64
    float* B3s  = B2s + 64;               // 64

    const int tid = threadIdx.x;
    const int m  = blockIdx.x >> 2;
    const int j0 = (blockIdx.x & 3) << 4;

    // stage table (fp16, 64.4KB) + v1 + biases
    {
        const uint4* ts = (const uint4*)g_table_h;
        uint4* td = (uint4*)TABu;
        #pragma unroll
        for (int r = 0; r < 4; r++) td[tid + r * 1024] = ts[tid + r * 1024];
        if (tid < 24) td[4096 + tid] = ts[4096 + tid];
        ((float4*)V1s)[tid] = ((const float4*)(g_v1 + m * 4096))[tid];
        if (tid < 64) B2s[tid] = b2[tid];
        else if (tid < 128) B3s[tid - 64] = b3[tid - 64];
    }
    // per-pair quadratic weights around nearest node k (nodes k-1,k,k+1)
    {
        const int p = tid;
        const int i = p >> 4, jj = p & 15;
        float d = dist[(m * 64 + i) * 64 + j0 + jj];
        float t = d * INV_H;
        int k = __float2int_rn(t);
        k = min(max(k, 1), S_INT - 1);
        float u = t - (float)k;
        float wm = 0.5f * u * (u - 1.0f);
        float w0 = 1.0f - u * u;
        float wp = 0.5f * u * (u + 1.0f);
        float4 wk;
        wk.x = __uint_as_float(h2bits(wm));
        wk.y = __uint_as_float(h2bits(w0));
        wk.z = __uint_as_float(h2bits(wp));
        wk.w = __int_as_float((k - 1) << 7);   // byte offset of first tap row
        ((float4*)W4s)[p] = wk;
    }
    __syncthreads();

    const int warp  = tid >> 5;
    const int jj    = warp & 15;     // destination atom
    const int ihalf = warp >> 4;     // 0..1 : i-range half
    const int t     = tid & 31;      // lane = channel pair (2t, 2t+1)

    u64 acc = 0ull;
    const char* tb = (const char*)TABu + (t << 2);
    const u64* V1v = (const u64*)V1s;
    const float4* W4v = ((const float4*)W4s) + jj;
    const int ibase = ihalf << 5;

    #pragma unroll 4
    for (int ii = 0; ii < 32; ii++) {
        const int i = ibase + ii;
        float4 wk = W4v[i << 4];                     // broadcast
        int koff = __float_as_int(wk.w);
        unsigned r0 = *(const unsigned*)(tb + koff);
        unsigned r1 = *(const unsigned*)(tb + koff + 128);
        unsigned r2 = *(const unsigned*)(tb + koff + 256);
        __half2 h2 = __hfma2(bits2h(__float_as_uint(wk.x)), bits2h(r0),
                     __hfma2(bits2h(__float_as_uint(wk.y)), bits2h(r1),
                     __hmul2(bits2h(__float_as_uint(wk.z)), bits2h(r2))));
        float2 hf = __half22float2(h2);
        u64 vv = V1v[(i << 5) + t];
        acc = fma2(vv, pack2(hf.x, hf.y), acc);
    }
    ((u64*)PARTs)[(ihalf << 9) + (jj << 5) + t] = acc;
    __syncthreads();

    // reduce 2-way partials; stage W2T/W3T into dead table region
    if (tid < 512) {
        u64 a = add2(((const u64*)PARTs)[tid], ((const u64*)PARTs)[tid + 512]);
        ((u64*)PAIRs)[tid] = a;
    }
    float* W2Ts = (float*)TABu;
    float* W3Ts = W2Ts + 4096;
    {
        ((float4*)W2Ts)[tid] = ((const float4*)g_W2t)[tid];
        ((float4*)W3Ts)[tid] = ((const float4*)g_W3t)[tid];
    }
    __syncthreads();

    // epilogue: 8 warps, each handles 2 j-rows; lane = output pair (2t,2t+1)
    if (tid < 256) {
        const int g  = tid >> 5;      // 0..7
        const int jj0 = g, jj1 = g + 8;

        // layer 2: v2 = softplus(PAIR @ W2^T + b2)
        u64 a0, a1;
        {
            u64 bp = ((const u64*)B2s)[t];
            a0 = bp; a1 = bp;
            const float4* pr0 = (const float4*)(PAIRs + jj0 * 64);
            const float4* pr1 = (const float4*)(PAIRs + jj1 * 64);
            const u64* wv = (const u64*)W2Ts;
            #pragma unroll 4
            for (int c4 = 0; c4 < 16; c4++) {
                float4 p0 = pr0[c4];
                float4 p1 = pr1[c4];
                u64 w0 = wv[(c4 * 4 + 0) * 32 + t];
                u64 w1 = wv[(c4 * 4 + 1) * 32 + t];
                u64 w2 = wv[(c4 * 4 + 2) * 32 + t];
                u64 w3 = wv[(c4 * 4 + 3) * 32 + t];
                a0 = fma2(dup2(p0.x), w0, a0); a1 = fma2(dup2(p1.x), w0, a1);
                a0 = fma2(dup2(p0.y), w1, a0); a1 = fma2(dup2(p1.y), w1, a1);
                a0 = fma2(dup2(p0.z), w2, a0); a1 = fma2(dup2(p1.z), w2, a1);
                a0 = fma2(dup2(p0.w), w3, a0); a1 = fma2(dup2(p1.w), w3, a1);
            }
            float2 f0 = unpk2(a0), f1 = unpk2(a1);
            ((u64*)V2s)[jj0 * 32 + t] = pack2(softplus_f(f0.x), softplus_f(f0.y));
            ((u64*)V2s)[jj1 * 32 + t] = pack2(softplus_f(f1.x), softplus_f(f1.y));
        }
        __syncwarp();

        // layer 3 + residual
        {
            u64 bp = ((const u64*)B3s)[t];
            a0 = bp; a1 = bp;
            const float4* pr0 = (const float4*)(V2s + jj0 * 64);
            const float4* pr1 = (const float4*)(V2s + jj1 * 64);
            const u64* wv = (const u64*)W3Ts;
            #pragma unroll 4
            for (int c4 = 0; c4 < 16; c4++) {
                float4 p0 = pr0[c4];
                float4 p1 = pr1[c4];
                u64 w0 = wv[(c4 * 4 + 0) * 32 + t];
                u64 w1 = wv[(c4 * 4 + 1) * 32 + t];
                u64 w2 = wv[(c4 * 4 + 2) * 32 + t];
                u64 w3 = wv[(c4 * 4 + 3) * 32 + t];
                a0 = fma2(dup2(p0.x), w0, a0); a1 = fma2(dup2(p1.x), w0, a1);
                a0 = fma2(dup2(p0.y), w1, a0); a1 = fma2(dup2(p1.y), w1, a1);
                a0 = fma2(dup2(p0.z), w2, a0); a1 = fma2(dup2(p1.z), w2, a1);
                a0 = fma2(dup2(p0.w), w3, a0); a1 = fma2(dup2(p1.w), w3, a1);
            }
            const u64* xv = (const u64*)x;
            u64* ov = (u64*)out;
            int g0 = (m * 64 + j0 + jj0) * 32 + t;
            int g1 = (m * 64 + j0 + jj1) * 32 + t;
            float2 f0 = unpk2(a0), x0 = unpk2(xv[g0]);
            float2 f1 = unpk2(a1), x1 = unpk2(xv[g1]);
            ov[g0] = pack2(f0.x + x0.x, f0.y + x0.y);
            ov[g1] = pack2(f1.x + x1.x, f1.y + x1.y);
        }
    }
}

extern "C" void kernel_launch(void* const* d_in, const int* in_sizes, int n_in,
                              void* d_out, int out_size) {
    const float* x   = (const float*)d_in[0];
    const float* dist= (const float*)d_in[1];
    const float* W1  = (const float*)d_in[2];
    const float* b1  = (const float*)d_in[3];
    const float* W2  = (const float*)d_in[4];
    const float* b2  = (const float*)d_in[5];
    const float* W3  = (const float*)d_in[6];
    const float* b3  = (const float*)d_in[7];
    const float* Wd1 = (const float*)d_in[8];
    const float* bd1 = (const float*)d_in[9];
    const float* Wd2 = (const float*)d_in[10];
    const float* bd2 = (const float*)d_in[11];
    float* out = (float*)d_out;
    (void)in_sizes; (void)n_in; (void)out_size;

    cudaFuncSetAttribute(prep_kernel, cudaFuncAttributeMaxDynamicSharedMemorySize, PREP_SMEM);
    cudaFuncSetAttribute(main_kernel, cudaFuncAttributeMaxDynamicSharedMemorySize, MAIN_SMEM);

    prep_kernel<<<PREP_BLOCKS, 512, PREP_SMEM>>>(x, W1, b1, W2, W3, Wd1, bd1, Wd2, bd2);
    main_kernel<<<128, 1024, MAIN_SMEM>>>(x, dist, b2, b3, out);
}

// round 10
// speedup vs baseline: 1.4307x; 1.4307x over previous
#include <cuda_runtime.h>
#include <cuda_fp16.h>
#include <math.h>

#define HIDDEN 64
#define MBATCH 32
#define ATOM   64
#define NUM_RBF 300

#define S_INT   512
#define TAB_ROWS 513                    // row s = h(s*H_STEP), s in [0,512]
#define H_STEP  (10.0f / 512.0f)
#define INV_H   51.2f

typedef unsigned long long u64;

// device scratch (no allocations allowed)
__device__ __align__(16) unsigned g_table_h[515 * 32];   // fp16x2 table, row=128B
__device__ __align__(16) float g_v1[MBATCH * ATOM * HIDDEN];
__device__ __align__(16) float g_W2t[HIDDEN * HIDDEN];
__device__ __align__(16) float g_W3t[HIDDEN * HIDDEN];

__device__ __forceinline__ float softplus_f(float v) {
    return fmaxf(v, 0.0f) + log1pf(expf(-fabsf(v)));
}

// packed f32x2 helpers (Blackwell FFMA2 / FADD2)
__device__ __forceinline__ u64 fma2(u64 a, u64 b, u64 c) {
    u64 d; asm("fma.rn.f32x2 %0, %1, %2, %3;" : "=l"(d) : "l"(a), "l"(b), "l"(c)); return d;
}
__device__ __forceinline__ u64 add2(u64 a, u64 b) {
    u64 d; asm("add.rn.f32x2 %0, %1, %2;" : "=l"(d) : "l"(a), "l"(b)); return d;
}
__device__ __forceinline__ u64 pack2(float a, float b) {
    u64 d; asm("mov.b64 %0, {%1, %2};" : "=l"(d) : "f"(a), "f"(b)); return d;
}
__device__ __forceinline__ float2 unpk2(u64 v) {
    float2 f; asm("mov.b64 {%0, %1}, %2;" : "=f"(f.x), "=f"(f.y) : "l"(v)); return f;
}
__device__ __forceinline__ u64 dup2(float v) {
    u64 d; asm("mov.b64 %0, {%1, %1};" : "=l"(d) : "f"(v)); return d;
}
__device__ __forceinline__ unsigned h2bits(float w) {
    __half2 h = __float2half2_rn(w);
    return *reinterpret_cast<unsigned*>(&h);
}
__device__ __forceinline__ __half2 bits2h(unsigned u) {
    return *reinterpret_cast<__half2*>(&u);
}

// ---------------------------------------------------------------------------
// Prep kernel, 512 threads/block (vectorized staging):
//   blocks [0,65):    h(d) table (fp16), 8 samples/block
//   blocks [65,129):  v1 = x@W1^T + b1
//   block 129:        transpose W2, W3
// ---------------------------------------------------------------------------
#define TAB_BLOCKS 65
#define V1_BLOCKS  64
#define PREP_BLOCKS (TAB_BLOCKS + V1_BLOCKS + 1)
#define PREP_SMEM ((64*301 + 64*65 + 8*304 + 8*64) * 4)

__global__ void __launch_bounds__(512) prep_kernel(
    const float* __restrict__ x,  const float* __restrict__ W1, const float* __restrict__ b1,
    const float* __restrict__ W2, const float* __restrict__ W3,
    const float* __restrict__ Wd1, const float* __restrict__ bd1,
    const float* __restrict__ Wd2, const float* __restrict__ bd2)
{
    extern __shared__ float sh[];
    const int tid = threadIdx.x;
    const int b = blockIdx.x;

    if (b < TAB_BLOCKS) {
        float* Wd1_s = sh;                   // 64 x 301 (padded)
        float* Wd2_s = Wd1_s + 64 * 301;     // 64 x 65
        float* rbf_s = Wd2_s + 64 * 65;      // 8 x 304
        float* g_s   = rbf_s + 8 * 304;      // 8 x 64

        {
            const float4* w4 = (const float4*)Wd1;
            #pragma unroll 4
            for (int idx = tid; idx < 4800; idx += 512) {
                float4 v = w4[idx];
                int e = idx << 2;
                int cc = e / NUM_RBF;
                int r  = e - cc * NUM_RBF;
                float* dstp = Wd1_s + cc * 301 + r;
                dstp[0] = v.x; dstp[1] = v.y; dstp[2] = v.z; dstp[3] = v.w;
            }
        }
        {
            const float4* w4 = (const float4*)Wd2;
            #pragma unroll 2
            for (int idx = tid; idx < 1024; idx += 512) {
                float4 v = w4[idx];
                int e = idx << 2;
                float* dstp = Wd2_s + (e >> 6) * 65 + (e & 63);
                dstp[0] = v.x; dstp[1] = v.y; dstp[2] = v.z; dstp[3] = v.w;
            }
        }
        const int s0 = b * 8;
        #pragma unroll 2
        for (int idx = tid; idx < 8 * NUM_RBF; idx += 512) {
            int qq = idx / NUM_RBF;
            int r  = idx - qq * NUM_RBF;
            float dd = (float)(s0 + qq) * H_STEP;
            float u = dd - 0.1f * (float)r;
            rbf_s[qq * 304 + r] = __expf(-10.0f * u * u);
        }
        __syncthreads();

        const int q = tid >> 6;
        const int c = tid & 63;
        const int s = s0 + q;
        const float d = (float)s * H_STEP;
        int rlo = (int)ceilf((d - 1.5f) * 10.0f); if (rlo < 0) rlo = 0;
        int rhi = (int)floorf((d + 1.5f) * 10.0f); if (rhi > NUM_RBF - 1) rhi = NUM_RBF - 1;
        float p = bd1[c];
        const float* wrow = Wd1_s + c * 301;
        const float* rrow = rbf_s + q * 304;
        #pragma unroll 4
        for (int r = rlo; r <= rhi; r++) p = fmaf(wrow[r], rrow[r], p);
        g_s[q * 64 + c] = softplus_f(p);
        __syncthreads();

        float qv = bd2[c];
        const float* w2row = Wd2_s + c * 65;
        const float* gg = g_s + q * 64;
        #pragma unroll 8
        for (int k = 0; k < 64; k++) qv = fmaf(w2row[k], gg[k], qv);
        if (s < TAB_ROWS)
            ((__half*)g_table_h)[s * 64 + c] = __float2half_rn(softplus_f(qv));
    } else if (b < TAB_BLOCKS + V1_BLOCKS) {
        const int v = b - TAB_BLOCKS;
        const int m = v >> 1, half = v & 1;
        float* W1p = sh;                 // 64 x 68 padded
        float* xp  = sh + 64 * 68;       // 32 x 68

        {
            const float4* w4 = (const float4*)W1;
            #pragma unroll 2
            for (int idx = tid; idx < 1024; idx += 512) {
                float4 vv = w4[idx];
                int e = idx << 2;
                float* dstp = W1p + (e >> 6) * 68 + (e & 63);
                dstp[0] = vv.x; dstp[1] = vv.y; dstp[2] = vv.z; dstp[3] = vv.w;
            }
            const float4* x4 = (const float4*)(x + m * 4096 + half * 2048);
            {
                float4 vv = x4[tid];
                int e = tid << 2;
                float* dstp = xp + (e >> 6) * 68 + (e & 63);
                dstp[0] = vv.x; dstp[1] = vv.y; dstp[2] = vv.z; dstp[3] = vv.w;
            }
        }
        __syncthreads();

        const int ii = tid & 31;
        const int oh = tid >> 5;
        float4 acc = make_float4(0.f, 0.f, 0.f, 0.f);
        const float* xr = xp + ii * 68;
        const float* wr = W1p + oh * 4 * 68;
        #pragma unroll
        for (int c4 = 0; c4 < 16; c4++) {
            float4 xv = *(const float4*)(xr + c4 * 4);
            float4 w0 = *(const float4*)(wr + 0 * 68 + c4 * 4);
            float4 w1 = *(const float4*)(wr + 1 * 68 + c4 * 4);
            float4 w2 = *(const float4*)(wr + 2 * 68 + c4 * 4);
            float4 w3 = *(const float4*)(wr + 3 * 68 + c4 * 4);
            acc.x = fmaf(xv.x, w0.x, fmaf(xv.y, w0.y, fmaf(xv.z, w0.z, fmaf(xv.w, w0.w, acc.x))));
            acc.y = fmaf(xv.x, w1.x, fmaf(xv.y, w1.y, fmaf(xv.z, w1.z, fmaf(xv.w, w1.w, acc.y))));
            acc.z = fmaf(xv.x, w2.x, fmaf(xv.y, w2.y, fmaf(xv.z, w2.z, fmaf(xv.w, w2.w, acc.z))));
            acc.w = fmaf(xv.x, w3.x, fmaf(xv.y, w3.y, fmaf(xv.z, w3.z, fmaf(xv.w, w3.w, acc.w))));
        }
        float4 bv = *(const float4*)(b1 + oh * 4);
        acc.x += bv.x; acc.y += bv.y; acc.z += bv.z; acc.w += bv.w;
        *(float4*)(g_v1 + (m * 64 + half * 32 + ii) * 64 + oh * 4) = acc;
    } else {
        #pragma unroll 8
        for (int idx = tid; idx < 8192; idx += 512) {
            const float* src = (idx < 4096) ? W2 : W3;
            float* dst = (idx < 4096) ? g_W2t : g_W3t;
            int e = idx & 4095;
            dst[(e & 63) * 64 + (e >> 6)] = src[e];
        }
    }
}

// ---------------------------------------------------------------------------
// Main kernel: 128 blocks = (m, j-group of 16), 1024 threads (32 warps).
// Half-warp channel-quad scheme: lane = (half, quad q); warp = (ihalf, jj);
// each warp-iteration processes TWO pairs (even/odd i per half-warp) with
// only 5 LDS instructions (2.5 per pair). Quadratic 3-tap fp16 interp.
// ---------------------------------------------------------------------------
// smem floats: TAB 16480 | V1 4096 | W4 4096 | PART 4096 | PAIR 1024 |
// V2 1024 | B2 64 | B3 64 = 30944 floats = 123776 B
#define MAIN_SMEM (30944 * 4)

__global__ void __launch_bounds__(1024) main_kernel(
    const float* __restrict__ x, const float* __restrict__ dist,
    const float* __restrict__ b2, const float* __restrict__ b3,
    float* __restrict__ out)
{
    extern __shared__ float sh[];
    unsigned* TABu = (unsigned*)sh;       // fp16 table; reused as W2T/W3T later
    float* V1s  = sh + 16480;             // 4096
    float* W4s  = V1s + 4096;             // 4096 : per-pair (wm,w0,wp h2-bits, koff)
    float* PARTs= W4s + 4096;             // 4096 : 4-slice ulonglong2 partials
    float* PAIRs= PARTs + 4096;           // 1024
    float* V2s  = PAIRs + 1024;           // 1024
    float* B2s  = V2s + 1024;             // 64
    float* B3s  = B2s + 64;               // 64

    const int tid = threadIdx.x;
    const int m  = blockIdx.x >> 2;
    const int j0 = (blockIdx.x & 3) << 4;

    // stage table (fp16, 64.4KB) + v1 + biases
    {
        const uint4* ts = (const uint4*)g_table_h;
        uint4* td = (uint4*)TABu;
        #pragma unroll
        for (int r = 0; r < 4; r++) td[tid + r * 1024] = ts[tid + r * 1024];
        if (tid < 24) td[4096 + tid] = ts[4096 + tid];
        ((float4*)V1s)[tid] = ((const float4*)(g_v1 + m * 4096))[tid];
        if (tid < 64) B2s[tid] = b2[tid];
        else if (tid < 128) B3s[tid - 64] = b3[tid - 64];
    }
    // per-pair quadratic weights around nearest node k (nodes k-1,k,k+1)
    {
        const int p = tid;
        const int i = p >> 4, jj = p & 15;
        float d = dist[(m * 64 + i) * 64 + j0 + jj];
        float t = d * INV_H;
        int k = __float2int_rn(t);
        k = min(max(k, 1), S_INT - 1);
        float u = t - (float)k;
        float wm = 0.5f * u * (u - 1.0f);
        float w0 = 1.0f - u * u;
        float wp = 0.5f * u * (u + 1.0f);
        float4 wk;
        wk.x = __uint_as_float(h2bits(wm));
        wk.y = __uint_as_float(h2bits(w0));
        wk.z = __uint_as_float(h2bits(wp));
        wk.w = __int_as_float((k - 1) << 7);   // byte offset of first tap row
        ((float4*)W4s)[p] = wk;
    }
    __syncthreads();

    const int warp  = tid >> 5;
    const int jj    = warp & 15;     // destination atom
    const int ihalf = warp >> 4;     // 0..1 : i-range half
    const int t     = tid & 31;
    const int half  = t >> 4;        // even/odd i within the half-warp
    const int q     = t & 15;        // channel quad: channels 4q..4q+3

    u64 acc0 = 0ull, acc1 = 0ull;
    const char* tb = (const char*)TABu + (q << 3);          // 8B per quad
    const char* v1b = (const char*)V1s + (q << 4);          // 16B per quad
    const float4* W4v = ((const float4*)W4s) + jj;
    const int i0 = (ihalf << 5) + half;                     // start i, step 2

    #pragma unroll 4
    for (int ii = 0; ii < 16; ii++) {
        const int i = i0 + (ii << 1);
        float4 wk = W4v[i << 4];                            // bcast per half-warp
        int koff = __float_as_int(wk.w);
        uint2 r0 = *(const uint2*)(tb + koff);
        uint2 r1 = *(const uint2*)(tb + koff + 128);
        uint2 r2 = *(const uint2*)(tb + koff + 256);
        ulonglong2 vv = *(const ulonglong2*)(v1b + (i << 8));
        __half2 wm2 = bits2h(__float_as_uint(wk.x));
        __half2 w02 = bits2h(__float_as_uint(wk.y));
        __half2 wp2 = bits2h(__float_as_uint(wk.z));
        __half2 hA = __hfma2(wm2, bits2h(r0.x),
                     __hfma2(w02, bits2h(r1.x), __hmul2(wp2, bits2h(r2.x))));
        __half2 hB = __hfma2(wm2, bits2h(r0.y),
                     __hfma2(w02, bits2h(r1.y), __hmul2(wp2, bits2h(r2.y))));
        float2 fA = __half22float2(hA);
        float2 fB = __half22float2(hB);
        acc0 = fma2(vv.x, pack2(fA.x, fA.y), acc0);
        acc1 = fma2(vv.y, pack2(fB.x, fB.y), acc1);
    }
    {
        const int slice = (ihalf << 1) | half;              // 0..3
        ulonglong2 r; r.x = acc0; r.y = acc1;
        ((ulonglong2*)PARTs)[slice * 256 + (jj << 4) + q] = r;
    }
    __syncthreads();

    // reduce 4 slices; stage W2T/W3T into dead table region
    if (tid < 256) {
        const ulonglong2* pp = (const ulonglong2*)PARTs;
        ulonglong2 a0 = pp[tid];
        ulonglong2 a1 = pp[256 + tid];
        ulonglong2 a2 = pp[512 + tid];
        ulonglong2 a3 = pp[768 + tid];
        ulonglong2 r;
        r.x = add2(add2(a0.x, a1.x), add2(a2.x, a3.x));
        r.y = add2(add2(a0.y, a1.y), add2(a2.y, a3.y));
        ((ulonglong2*)PAIRs)[tid] = r;
    }
    float* W2Ts = (float*)TABu;
    float* W3Ts = W2Ts + 4096;
    {
        ((float4*)W2Ts)[tid] = ((const float4*)g_W2t)[tid];
        ((float4*)W3Ts)[tid] = ((const float4*)g_W3t)[tid];
    }
    __syncthreads();

    // epilogue: 8 warps, each handles 2 j-rows; lane = output pair (2t,2t+1)
    if (tid < 256) {
        const int g  = tid >> 5;      // 0..7
        const int tt = tid & 31;
        const int jj0 = g, jj1 = g + 8;

        u64 a0, a1;
        {
            u64 bp = ((const u64*)B2s)[tt];
            a0 = bp; a1 = bp;
            const float4* pr0 = (const float4*)(PAIRs + jj0 * 64);
            const float4* pr1 = (const float4*)(PAIRs + jj1 * 64);
            const u64* wv = (const u64*)W2Ts;
            #pragma unroll 4
            for (int c4 = 0; c4 < 16; c4++) {
                float4 p0 = pr0[c4];
                float4 p1 = pr1[c4];
                u64 w0 = wv[(c4 * 4 + 0) * 32 + tt];
                u64 w1 = wv[(c4 * 4 + 1) * 32 + tt];
                u64 w2 = wv[(c4 * 4 + 2) * 32 + tt];
                u64 w3 = wv[(c4 * 4 + 3) * 32 + tt];
                a0 = fma2(dup2(p0.x), w0, a0); a1 = fma2(dup2(p1.x), w0, a1);
                a0 = fma2(dup2(p0.y), w1, a0); a1 = fma2(dup2(p1.y), w1, a1);
                a0 = fma2(dup2(p0.z), w2, a0); a1 = fma2(dup2(p1.z), w2, a1);
                a0 = fma2(dup2(p0.w), w3, a0); a1 = fma2(dup2(p1.w), w3, a1);
            }
            float2 f0 = unpk2(a0), f1 = unpk2(a1);
            ((u64*)V2s)[jj0 * 32 + tt] = pack2(softplus_f(f0.x), softplus_f(f0.y));
            ((u64*)V2s)[jj1 * 32 + tt] = pack2(softplus_f(f1.x), softplus_f(f1.y));
        }
        __syncwarp();

        {
            u64 bp = ((const u64*)B3s)[tt];
            a0 = bp; a1 = bp;
            const float4* pr0 = (const float4*)(V2s + jj0 * 64);
            const float4* pr1 = (const float4*)(V2s + jj1 * 64);
            const u64* wv = (const u64*)W3Ts;
            #pragma unroll 4
            for (int c4 = 0; c4 < 16; c4++) {
                float4 p0 = pr0[c4];
                float4 p1 = pr1[c4];
                u64 w0 = wv[(c4 * 4 + 0) * 32 + tt];
                u64 w1 = wv[(c4 * 4 + 1) * 32 + tt];
                u64 w2 = wv[(c4 * 4 + 2) * 32 + tt];
                u64 w3 = wv[(c4 * 4 + 3) * 32 + tt];
                a0 = fma2(dup2(p0.x), w0, a0); a1 = fma2(dup2(p1.x), w0, a1);
                a0 = fma2(dup2(p0.y), w1, a0); a1 = fma2(dup2(p1.y), w1, a1);
                a0 = fma2(dup2(p0.z), w2, a0); a1 = fma2(dup2(p1.z), w2, a1);
                a0 = fma2(dup2(p0.w), w3, a0); a1 = fma2(dup2(p1.w), w3, a1);
            }
            const u64* xv = (const u64*)x;
            u64* ov = (u64*)out;
            int g0 = (m * 64 + j0 + jj0) * 32 + tt;
            int g1 = (m * 64 + j0 + jj1) * 32 + tt;
            float2 f0 = unpk2(a0), x0 = unpk2(xv[g0]);
            float2 f1 = unpk2(a1), x1 = unpk2(xv[g1]);
            ov[g0] = pack2(f0.x + x0.x, f0.y + x0.y);
            ov[g1] = pack2(f1.x + x1.x, f1.y + x1.y);
        }
    }
}

extern "C" void kernel_launch(void* const* d_in, const int* in_sizes, int n_in,
                              void* d_out, int out_size) {
    const float* x   = (const float*)d_in[0];
    const float* dist= (const float*)d_in[1];
    const float* W1  = (const float*)d_in[2];
    const float* b1  = (const float*)d_in[3];
    const float* W2  = (const float*)d_in[4];
    const float* b2  = (const float*)d_in[5];
    const float* W3  = (const float*)d_in[6];
    const float* b3  = (const float*)d_in[7];
    const float* Wd1 = (const float*)d_in[8];
    const float* bd1 = (const float*)d_in[9];
    const float* Wd2 = (const float*)d_in[10];
    const float* bd2 = (const float*)d_in[11];
    float* out = (float*)d_out;
    (void)in_sizes; (void)n_in; (void)out_size;

    cudaFuncSetAttribute(prep_kernel, cudaFuncAttributeMaxDynamicSharedMemorySize, PREP_SMEM);
    cudaFuncSetAttribute(main_kernel, cudaFuncAttributeMaxDynamicSharedMemorySize, MAIN_SMEM);

    prep_kernel<<<PREP_BLOCKS, 512, PREP_SMEM>>>(x, W1, b1, W2, W3, Wd1, bd1, Wd2, bd2);
    main_kernel<<<128, 1024, MAIN_SMEM>>>(x, dist, b2, b3, out);
}

// round 11
// speedup vs baseline: 1.4476x; 1.0118x over previous
#include <cuda_runtime.h>
#include <cuda_fp16.h>
#include <math.h>

#define HIDDEN 64
#define MBATCH 32
#define ATOM   64
#define NUM_RBF 300

#define S_INT   512
#define TAB_ROWS 513                    // row s = h(s*H_STEP), s in [0,512]
#define H_STEP  (10.0f / 512.0f)
#define INV_H   51.2f

typedef unsigned long long u64;

// device scratch (no allocations allowed)
__device__ __align__(16) unsigned g_table_h[515 * 32];   // fp16x2 table, row=128B
__device__ __align__(16) float g_v1[MBATCH * ATOM * HIDDEN];
__device__ __align__(16) float g_W2t[HIDDEN * HIDDEN];
__device__ __align__(16) float g_W3t[HIDDEN * HIDDEN];

__device__ __forceinline__ float softplus_f(float v) {
    return fmaxf(v, 0.0f) + log1pf(expf(-fabsf(v)));
}

// packed f32x2 helpers (Blackwell FFMA2 / FADD2)
__device__ __forceinline__ u64 fma2(u64 a, u64 b, u64 c) {
    u64 d; asm("fma.rn.f32x2 %0, %1, %2, %3;" : "=l"(d) : "l"(a), "l"(b), "l"(c)); return d;
}
__device__ __forceinline__ u64 add2(u64 a, u64 b) {
    u64 d; asm("add.rn.f32x2 %0, %1, %2;" : "=l"(d) : "l"(a), "l"(b)); return d;
}
__device__ __forceinline__ u64 pack2(float a, float b) {
    u64 d; asm("mov.b64 %0, {%1, %2};" : "=l"(d) : "f"(a), "f"(b)); return d;
}
__device__ __forceinline__ float2 unpk2(u64 v) {
    float2 f; asm("mov.b64 {%0, %1}, %2;" : "=f"(f.x), "=f"(f.y) : "l"(v)); return f;
}
__device__ __forceinline__ u64 dup2(float v) {
    u64 d; asm("mov.b64 %0, {%1, %1};" : "=l"(d) : "f"(v)); return d;
}
__device__ __forceinline__ unsigned h2bits(float w) {
    __half2 h = __float2half2_rn(w);
    return *reinterpret_cast<unsigned*>(&h);
}
__device__ __forceinline__ __half2 bits2h(unsigned u) {
    return *reinterpret_cast<__half2*>(&u);
}

// ---------------------------------------------------------------------------
// Prep kernel (unchanged from R10), 512 threads/block
// ---------------------------------------------------------------------------
#define TAB_BLOCKS 65
#define V1_BLOCKS  64
#define PREP_BLOCKS (TAB_BLOCKS + V1_BLOCKS + 1)
#define PREP_SMEM ((64*301 + 64*65 + 8*304 + 8*64) * 4)

__global__ void __launch_bounds__(512) prep_kernel(
    const float* __restrict__ x,  const float* __restrict__ W1, const float* __restrict__ b1,
    const float* __restrict__ W2, const float* __restrict__ W3,
    const float* __restrict__ Wd1, const float* __restrict__ bd1,
    const float* __restrict__ Wd2, const float* __restrict__ bd2)
{
    extern __shared__ float sh[];
    const int tid = threadIdx.x;
    const int b = blockIdx.x;

    if (b < TAB_BLOCKS) {
        float* Wd1_s = sh;                   // 64 x 301 (padded)
        float* Wd2_s = Wd1_s + 64 * 301;     // 64 x 65
        float* rbf_s = Wd2_s + 64 * 65;      // 8 x 304
        float* g_s   = rbf_s + 8 * 304;      // 8 x 64

        {
            const float4* w4 = (const float4*)Wd1;
            #pragma unroll 4
            for (int idx = tid; idx < 4800; idx += 512) {
                float4 v = w4[idx];
                int e = idx << 2;
                int cc = e / NUM_RBF;
                int r  = e - cc * NUM_RBF;
                float* dstp = Wd1_s + cc * 301 + r;
                dstp[0] = v.x; dstp[1] = v.y; dstp[2] = v.z; dstp[3] = v.w;
            }
        }
        {
            const float4* w4 = (const float4*)Wd2;
            #pragma unroll 2
            for (int idx = tid; idx < 1024; idx += 512) {
                float4 v = w4[idx];
                int e = idx << 2;
                float* dstp = Wd2_s + (e >> 6) * 65 + (e & 63);
                dstp[0] = v.x; dstp[1] = v.y; dstp[2] = v.z; dstp[3] = v.w;
            }
        }
        const int s0 = b * 8;
        #pragma unroll 2
        for (int idx = tid; idx < 8 * NUM_RBF; idx += 512) {
            int qq = idx / NUM_RBF;
            int r  = idx - qq * NUM_RBF;
            float dd = (float)(s0 + qq) * H_STEP;
            float u = dd - 0.1f * (float)r;
            rbf_s[qq * 304 + r] = __expf(-10.0f * u * u);
        }
        __syncthreads();

        const int q = tid >> 6;
        const int c = tid & 63;
        const int s = s0 + q;
        const float d = (float)s * H_STEP;
        int rlo = (int)ceilf((d - 1.5f) * 10.0f); if (rlo < 0) rlo = 0;
        int rhi = (int)floorf((d + 1.5f) * 10.0f); if (rhi > NUM_RBF - 1) rhi = NUM_RBF - 1;
        float p = bd1[c];
        const float* wrow = Wd1_s + c * 301;
        const float* rrow = rbf_s + q * 304;
        #pragma unroll 4
        for (int r = rlo; r <= rhi; r++) p = fmaf(wrow[r], rrow[r], p);
        g_s[q * 64 + c] = softplus_f(p);
        __syncthreads();

        float qv = bd2[c];
        const float* w2row = Wd2_s + c * 65;
        const float* gg = g_s + q * 64;
        #pragma unroll 8
        for (int k = 0; k < 64; k++) qv = fmaf(w2row[k], gg[k], qv);
        if (s < TAB_ROWS)
            ((__half*)g_table_h)[s * 64 + c] = __float2half_rn(softplus_f(qv));
    } else if (b < TAB_BLOCKS + V1_BLOCKS) {
        const int v = b - TAB_BLOCKS;
        const int m = v >> 1, half = v & 1;
        float* W1p = sh;                 // 64 x 68 padded
        float* xp  = sh + 64 * 68;       // 32 x 68

        {
            const float4* w4 = (const float4*)W1;
            #pragma unroll 2
            for (int idx = tid; idx < 1024; idx += 512) {
                float4 vv = w4[idx];
                int e = idx << 2;
                float* dstp = W1p + (e >> 6) * 68 + (e & 63);
                dstp[0] = vv.x; dstp[1] = vv.y; dstp[2] = vv.z; dstp[3] = vv.w;
            }
            const float4* x4 = (const float4*)(x + m * 4096 + half * 2048);
            {
                float4 vv = x4[tid];
                int e = tid << 2;
                float* dstp = xp + (e >> 6) * 68 + (e & 63);
                dstp[0] = vv.x; dstp[1] = vv.y; dstp[2] = vv.z; dstp[3] = vv.w;
            }
        }
        __syncthreads();

        const int ii = tid & 31;
        const int oh = tid >> 5;
        float4 acc = make_float4(0.f, 0.f, 0.f, 0.f);
        const float* xr = xp + ii * 68;
        const float* wr = W1p + oh * 4 * 68;
        #pragma unroll
        for (int c4 = 0; c4 < 16; c4++) {
            float4 xv = *(const float4*)(xr + c4 * 4);
            float4 w0 = *(const float4*)(wr + 0 * 68 + c4 * 4);
            float4 w1 = *(const float4*)(wr + 1 * 68 + c4 * 4);
            float4 w2 = *(const float4*)(wr + 2 * 68 + c4 * 4);
            float4 w3 = *(const float4*)(wr + 3 * 68 + c4 * 4);
            acc.x = fmaf(xv.x, w0.x, fmaf(xv.y, w0.y, fmaf(xv.z, w0.z, fmaf(xv.w, w0.w, acc.x))));
            acc.y = fmaf(xv.x, w1.x, fmaf(xv.y, w1.y, fmaf(xv.z, w1.z, fmaf(xv.w, w1.w, acc.y))));
            acc.z = fmaf(xv.x, w2.x, fmaf(xv.y, w2.y, fmaf(xv.z, w2.z, fmaf(xv.w, w2.w, acc.z))));
            acc.w = fmaf(xv.x, w3.x, fmaf(xv.y, w3.y, fmaf(xv.z, w3.z, fmaf(xv.w, w3.w, acc.w))));
        }
        float4 bv = *(const float4*)(b1 + oh * 4);
        acc.x += bv.x; acc.y += bv.y; acc.z += bv.z; acc.w += bv.w;
        *(float4*)(g_v1 + (m * 64 + half * 32 + ii) * 64 + oh * 4) = acc;
    } else {
        #pragma unroll 8
        for (int idx = tid; idx < 8192; idx += 512) {
            const float* src = (idx < 4096) ? W2 : W3;
            float* dst = (idx < 4096) ? g_W2t : g_W3t;
            int e = idx & 4095;
            dst[(e & 63) * 64 + (e >> 6)] = src[e];
        }
    }
}

// ---------------------------------------------------------------------------
// Main kernel: 128 blocks = (m, j-group of 16), 1024 threads (32 warps).
// Table taps read DIRECTLY from global (L1-cached, coalesced 128B rows) —
// no table staging. Half-warp channel-quad scheme as R10 (2 pairs / warp-iter,
// quadratic 3-tap fp16 interp). Epilogue weights staged once at start.
// ---------------------------------------------------------------------------
// smem floats: V1 4096 | W4 4096 | W2T 4096 | W3T 4096 | PART 4096 |
// PAIR 1024 | V2 1024 | B2 64 | B3 64 = 22656 floats = 90624 B
#define MAIN_SMEM (22656 * 4)

__global__ void __launch_bounds__(1024) main_kernel(
    const float* __restrict__ x, const float* __restrict__ dist,
    const float* __restrict__ b2, const float* __restrict__ b3,
    float* __restrict__ out)
{
    extern __shared__ float sh[];
    float* V1s  = sh;                     // 4096
    float* W4s  = V1s + 4096;             // 4096 : per-pair (wm,w0,wp h2-bits, koff)
    float* W2Ts = W4s + 4096;             // 4096
    float* W3Ts = W2Ts + 4096;            // 4096
    float* PARTs= W3Ts + 4096;            // 4096 : 4-slice ulonglong2 partials
    float* PAIRs= PARTs + 4096;           // 1024
    float* V2s  = PAIRs + 1024;           // 1024
    float* B2s  = V2s + 1024;             // 64
    float* B3s  = B2s + 64;               // 64

    const int tid = threadIdx.x;
    const int m  = blockIdx.x >> 2;
    const int j0 = (blockIdx.x & 3) << 4;

    // stage v1 + epilogue weights + biases (one float4 per thread each)
    {
        ((float4*)V1s)[tid]  = ((const float4*)(g_v1 + m * 4096))[tid];
        ((float4*)W2Ts)[tid] = ((const float4*)g_W2t)[tid];
        ((float4*)W3Ts)[tid] = ((const float4*)g_W3t)[tid];
        if (tid < 64) B2s[tid] = b2[tid];
        else if (tid < 128) B3s[tid - 64] = b3[tid - 64];
    }
    // per-pair quadratic weights around nearest node k (nodes k-1,k,k+1)
    {
        const int p = tid;
        const int i = p >> 4, jj = p & 15;
        float d = dist[(m * 64 + i) * 64 + j0 + jj];
        float t = d * INV_H;
        int k = __float2int_rn(t);
        k = min(max(k, 1), S_INT - 1);
        float u = t - (float)k;
        float wm = 0.5f * u * (u - 1.0f);
        float w0 = 1.0f - u * u;
        float wp = 0.5f * u * (u + 1.0f);
        float4 wk;
        wk.x = __uint_as_float(h2bits(wm));
        wk.y = __uint_as_float(h2bits(w0));
        wk.z = __uint_as_float(h2bits(wp));
        wk.w = __int_as_float((k - 1) << 7);   // byte offset of first tap row
        ((float4*)W4s)[p] = wk;
    }
    __syncthreads();

    const int warp  = tid >> 5;
    const int jj    = warp & 15;     // destination atom
    const int ihalf = warp >> 4;     // 0..1 : i-range half
    const int t     = tid & 31;
    const int half  = t >> 4;        // even/odd i within the half-warp
    const int q     = t & 15;        // channel quad: channels 4q..4q+3

    u64 acc0 = 0ull, acc1 = 0ull;
    const char* tbg = (const char*)g_table_h + (q << 3);    // GLOBAL, L1-cached
    const char* v1b = (const char*)V1s + (q << 4);
    const float4* W4v = ((const float4*)W4s) + jj;
    const int i0 = (ihalf << 5) + half;                     // start i, step 2

    #pragma unroll 4
    for (int ii = 0; ii < 16; ii++) {
        const int i = i0 + (ii << 1);
        float4 wk = W4v[i << 4];                            // bcast per half-warp
        int koff = __float_as_int(wk.w);
        uint2 r0 = __ldg((const uint2*)(tbg + koff));
        uint2 r1 = __ldg((const uint2*)(tbg + koff + 128));
        uint2 r2 = __ldg((const uint2*)(tbg + koff + 256));
        ulonglong2 vv = *(const ulonglong2*)(v1b + (i << 8));
        __half2 wm2 = bits2h(__float_as_uint(wk.x));
        __half2 w02 = bits2h(__float_as_uint(wk.y));
        __half2 wp2 = bits2h(__float_as_uint(wk.z));
        __half2 hA = __hfma2(wm2, bits2h(r0.x),
                     __hfma2(w02, bits2h(r1.x), __hmul2(wp2, bits2h(r2.x))));
        __half2 hB = __hfma2(wm2, bits2h(r0.y),
                     __hfma2(w02, bits2h(r1.y), __hmul2(wp2, bits2h(r2.y))));
        float2 fA = __half22float2(hA);
        float2 fB = __half22float2(hB);
        acc0 = fma2(vv.x, pack2(fA.x, fA.y), acc0);
        acc1 = fma2(vv.y, pack2(fB.x, fB.y), acc1);
    }
    {
        const int slice = (ihalf << 1) | half;              // 0..3
        ulonglong2 r; r.x = acc0; r.y = acc1;
        ((ulonglong2*)PARTs)[slice * 256 + (jj << 4) + q] = r;
    }
    __syncthreads();

    // reduce 4 slices
    if (tid < 256) {
        const ulonglong2* pp = (const ulonglong2*)PARTs;
        ulonglong2 a0 = pp[tid];
        ulonglong2 a1 = pp[256 + tid];
        ulonglong2 a2 = pp[512 + tid];
        ulonglong2 a3 = pp[768 + tid];
        ulonglong2 r;
        r.x = add2(add2(a0.x, a1.x), add2(a2.x, a3.x));
        r.y = add2(add2(a0.y, a1.y), add2(a2.y, a3.y));
        ((ulonglong2*)PAIRs)[tid] = r;
    }
    __syncthreads();

    // epilogue: 8 warps, each handles 2 j-rows; lane = output pair (2t,2t+1)
    if (tid < 256) {
        const int g  = tid >> 5;      // 0..7
        const int tt = tid & 31;
        const int jj0 = g, jj1 = g + 8;

        u64 a0, a1;
        {
            u64 bp = ((const u64*)B2s)[tt];
            a0 = bp; a1 = bp;
            const float4* pr0 = (const float4*)(PAIRs + jj0 * 64);
            const float4* pr1 = (const float4*)(PAIRs + jj1 * 64);
            const u64* wv = (const u64*)W2Ts;
            #pragma unroll 4
            for (int c4 = 0; c4 < 16; c4++) {
                float4 p0 = pr0[c4];
                float4 p1 = pr1[c4];
                u64 w0 = wv[(c4 * 4 + 0) * 32 + tt];
                u64 w1 = wv[(c4 * 4 + 1) * 32 + tt];
                u64 w2 = wv[(c4 * 4 + 2) * 32 + tt];
                u64 w3 = wv[(c4 * 4 + 3) * 32 + tt];
                a0 = fma2(dup2(p0.x), w0, a0); a1 = fma2(dup2(p1.x), w0, a1);
                a0 = fma2(dup2(p0.y), w1, a0); a1 = fma2(dup2(p1.y), w1, a1);
                a0 = fma2(dup2(p0.z), w2, a0); a1 = fma2(dup2(p1.z), w2, a1);
                a0 = fma2(dup2(p0.w), w3, a0); a1 = fma2(dup2(p1.w), w3, a1);
            }
            float2 f0 = unpk2(a0), f1 = unpk2(a1);
            ((u64*)V2s)[jj0 * 32 + tt] = pack2(softplus_f(f0.x), softplus_f(f0.y));
            ((u64*)V2s)[jj1 * 32 + tt] = pack2(softplus_f(f1.x), softplus_f(f1.y));
        }
        __syncwarp();

        {
            u64 bp = ((const u64*)B3s)[tt];
            a0 = bp; a1 = bp;
            const float4* pr0 = (const float4*)(V2s + jj0 * 64);
            const float4* pr1 = (const float4*)(V2s + jj1 * 64);
            const u64* wv = (const u64*)W3Ts;
            #pragma unroll 4
            for (int c4 = 0; c4 < 16; c4++) {
                float4 p0 = pr0[c4];
                float4 p1 = pr1[c4];
                u64 w0 = wv[(c4 * 4 + 0) * 32 + tt];
                u64 w1 = wv[(c4 * 4 + 1) * 32 + tt];
                u64 w2 = wv[(c4 * 4 + 2) * 32 + tt];
                u64 w3 = wv[(c4 * 4 + 3) * 32 + tt];
                a0 = fma2(dup2(p0.x), w0, a0); a1 = fma2(dup2(p1.x), w0, a1);
                a0 = fma2(dup2(p0.y), w1, a0); a1 = fma2(dup2(p1.y), w1, a1);
                a0 = fma2(dup2(p0.z), w2, a0); a1 = fma2(dup2(p1.z), w2, a1);
                a0 = fma2(dup2(p0.w), w3, a0); a1 = fma2(dup2(p1.w), w3, a1);
            }
            const u64* xv = (const u64*)x;
            u64* ov = (u64*)out;
            int g0 = (m * 64 + j0 + jj0) * 32 + tt;
            int g1 = (m * 64 + j0 + jj1) * 32 + tt;
            float2 f0 = unpk2(a0), x0 = unpk2(xv[g0]);
            float2 f1 = unpk2(a1), x1 = unpk2(xv[g1]);
            ov[g0] = pack2(f0.x + x0.x, f0.y + x0.y);
            ov[g1] = pack2(f1.x + x1.x, f1.y + x1.y);
        }
    }
}

extern "C" void kernel_launch(void* const* d_in, const int* in_sizes, int n_in,
                              void* d_out, int out_size) {
    const float* x   = (const float*)d_in[0];
    const float* dist= (const float*)d_in[1];
    const float* W1  = (const float*)d_in[2];
    const float* b1  = (const float*)d_in[3];
    const float* W2  = (const float*)d_in[4];
    const float* b2  = (const float*)d_in[5];
    const float* W3  = (const float*)d_in[6];
    const float* b3  = (const float*)d_in[7];
    const float* Wd1 = (const float*)d_in[8];
    const float* bd1 = (const float*)d_in[9];
    const float* Wd2 = (const float*)d_in[10];
    const float* bd2 = (const float*)d_in[11];
    float* out = (float*)d_out;
    (void)in_sizes; (void)n_in; (void)out_size;

    cudaFuncSetAttribute(prep_kernel, cudaFuncAttributeMaxDynamicSharedMemorySize, PREP_SMEM);
    cudaFuncSetAttribute(main_kernel, cudaFuncAttributeMaxDynamicSharedMemorySize, MAIN_SMEM);

    prep_kernel<<<PREP_BLOCKS, 512, PREP_SMEM>>>(x, W1, b1, W2, W3, Wd1, bd1, Wd2, bd2);
    main_kernel<<<128, 1024, MAIN_SMEM>>>(x, dist, b2, b3, out);
}